// round 15
// baseline (speedup 1.0000x reference)
#include <cuda_runtime.h>
#include <cuda_fp16.h>
#include <cstdint>
#include <math.h>

#define DM     1024
#define BATCHN 1024
#define HEADS  16
#define DK     64

// ---------------- scratch (no allocation allowed) ----------------
__device__ float g_qkv[3u * BATCHN * DM];            // q | k | v fp32
__device__ float g_beta[BATCHN * HEADS];
__device__ __half g_xh[BATCHN * DM];                 // x fp16
__device__ __half g_wt[4u * DM * DM];                // W^T fp16: Wq,Wk,Wv,Wo
__device__ __half g_ohh[BATCHN * DM];                // outh fp16

__device__ __forceinline__ uint32_t smaddr(const void* p) {
    uint32_t a;
    asm("{ .reg .u64 t; cvta.to.shared.u64 t, %1; cvt.u32.u64 %0, t; }" : "=r"(a) : "l"(p));
    return a;
}
__device__ __forceinline__ void cp16(uint32_t s, const void* g) {
    asm volatile("cp.async.cg.shared.global [%0], [%1], 16;" :: "r"(s), "l"(g));
}
__device__ __forceinline__ void cp4(uint32_t s, const void* g) {
    asm volatile("cp.async.ca.shared.global [%0], [%1], 4;" :: "r"(s), "l"(g));
}

// ---------------------------------------------------------------------------
// fused: x -> fp16  AND  beta = sigmoid(x @ Wg). One CTA/batch.
// ---------------------------------------------------------------------------
__global__ __launch_bounds__(256) void splitbeta_kernel(
    const float* __restrict__ x, __half* __restrict__ hi,
    const float* __restrict__ Wg, float* __restrict__ beta)
{
    __shared__ float xs[DM];
    const int b = blockIdx.x, t = threadIdx.x;
    const int idx = b * 256 + t;
    float4 v = reinterpret_cast<const float4*>(x)[idx];
    float f[4] = {v.x, v.y, v.z, v.w};
    __half h[4];
#pragma unroll
    for (int i = 0; i < 4; i++) {
        h[i] = __float2half_rn(f[i]);
        xs[t * 4 + i] = f[i];
    }
    __half2* h2 = reinterpret_cast<__half2*>(hi);
    h2[idx * 2 + 0] = __half2(h[0], h[1]);
    h2[idx * 2 + 1] = __half2(h[2], h[3]);
    __syncthreads();

    const int w = t >> 5, lane = t & 31;
    const int hh = w * 2 + (lane >> 4);        // head for this half-warp
    const int lj = lane & 15;
    float s = 0.f;
#pragma unroll 8
    for (int i = 0; i < 64; i++) {
        const int j = lj + (i << 4);
        s = fmaf(xs[j], Wg[j * HEADS + hh], s);
    }
#pragma unroll
    for (int off = 8; off; off >>= 1) s += __shfl_xor_sync(0xffffffffu, s, off);
    if (lj == 0) beta[b * HEADS + hh] = 1.f / (1.f + expf(-s));
}

// ---------------------------------------------------------------------------
// transpose + fp16: W[K][N] -> Wt[N][K] fp16. z selects matrix.
// ---------------------------------------------------------------------------
__global__ __launch_bounds__(256) void transhalf_kernel(
    const float* __restrict__ W0, const float* __restrict__ W1,
    const float* __restrict__ W2, const float* __restrict__ W3,
    __half* __restrict__ H)
{
    __shared__ float tile[32][33];
    const int z = blockIdx.z;
    const float* W = (z == 0) ? W0 : (z == 1) ? W1 : (z == 2) ? W2 : W3;
    __half* Ht = H + (size_t)z * DM * DM;
    const int tx = threadIdx.x & 31, ty = threadIdx.x >> 5;
    const int nb = blockIdx.x * 32, kb = blockIdx.y * 32;
#pragma unroll
    for (int i = 0; i < 4; i++) {
        int k = kb + ty + i * 8;
        tile[ty + i * 8][tx] = W[(size_t)k * DM + nb + tx];
    }
    __syncthreads();
#pragma unroll
    for (int i = 0; i < 4; i++) {
        int n = nb + ty + i * 8;
        Ht[(size_t)n * DM + kb + tx] = __float2half_rn(tile[tx][ty + i * 8]);
    }
}

// ---------------------------------------------------------------------------
// single-pass fp16 GEMM on mma.sync: C = A*B^T (fp32 accum).
// CTA tile 64xBN (BN=128 or 64), BK=32, 8 warps, 4-stage cp.async pipeline.
// ---------------------------------------------------------------------------
#define OFF_B 4096

__device__ __forceinline__ void mma_f16(float* c, const uint32_t* a, const uint32_t* b) {
    asm volatile(
        "mma.sync.aligned.m16n8k16.row.col.f32.f16.f16.f32 "
        "{%0,%1,%2,%3}, {%4,%5,%6,%7}, {%8,%9}, {%0,%1,%2,%3};"
        : "+f"(c[0]), "+f"(c[1]), "+f"(c[2]), "+f"(c[3])
        : "r"(a[0]), "r"(a[1]), "r"(a[2]), "r"(a[3]), "r"(b[0]), "r"(b[1]));
}

template<int BN>
__device__ __forceinline__ void cp_stage_t(
    uint32_t smStage, const char* aH, const char* bH, int ktBytes, int tid)
{
    {   // A: 64 rows x 64B = 256 chunks; thread t -> row t>>2, chunk t&3
        const int r = tid >> 2, c = tid & 3;
        const int sw = (r >> 1) & 3;
        const size_t goff = ((size_t)r << 11) + (size_t)ktBytes + (c << 4);
        const uint32_t soff = r * 64 + ((c ^ sw) << 4);
        cp16(smStage + soff, aH + goff);
    }
    if (BN == 128) {   // B: 128 rows; thread t -> row t>>1, chunks (t&1)*2,+1
        const int r = tid >> 1;
        const int sw = (r >> 1) & 3;
#pragma unroll
        for (int cc = 0; cc < 2; cc++) {
            const int c = (tid & 1) * 2 + cc;
            const size_t goff = ((size_t)r << 11) + (size_t)ktBytes + (c << 4);
            const uint32_t soff = r * 64 + ((c ^ sw) << 4);
            cp16(smStage + OFF_B + soff, bH + goff);
        }
    } else {           // B: 64 rows; thread t -> row t>>2, chunk t&3
        const int r = tid >> 2, c = tid & 3;
        const int sw = (r >> 1) & 3;
        const size_t goff = ((size_t)r << 11) + (size_t)ktBytes + (c << 4);
        const uint32_t soff = r * 64 + ((c ^ sw) << 4);
        cp16(smStage + OFF_B + soff, bH + goff);
    }
    asm volatile("cp.async.commit_group;");
}

template<int BN, int MINB>
__global__ __launch_bounds__(256, MINB) void mm_kernel(
    const __half* __restrict__ Ah,
    const __half* __restrict__ Bt0, const __half* __restrict__ Bt1,
    const __half* __restrict__ Bt2,
    float* __restrict__ C0, float* __restrict__ C1, float* __restrict__ C2,
    const float* __restrict__ bias)
{
    constexpr int STAGE = 4096 + BN * 64;
    constexpr int NI = BN / 32;
    extern __shared__ char sm[];
    uint32_t smbase;
    asm("{ .reg .u64 t; cvta.to.shared.u64 t, %1; cvt.u32.u64 %0, t; }"
        : "=r"(smbase) : "l"(sm));

    const int tid = threadIdx.x;
    const int warp = tid >> 5, lane = tid & 31;
    const int g = lane >> 2, tg = lane & 3;
    const int z = blockIdx.z;
    const __half* Bt = (z == 0) ? Bt0 : (z == 1) ? Bt1 : Bt2;
    float* C = (z == 0) ? C0 : (z == 1) ? C1 : C2;

    const int rowBase = blockIdx.y * 64;
    const int colBase = blockIdx.x * BN;
    const int warpRow = (warp & 1) * 32;
    const int warpCol = (warp >> 1) * (BN / 4);

    const char* aHp = (const char*)Ah + ((size_t)rowBase << 11);
    const char* bHp = (const char*)Bt + ((size_t)colBase << 11);

    const uint32_t sig = (uint32_t)(g & 6) << 3;
    const uint32_t kp[2][2] = { { (0u ^ sig),  (16u ^ sig) },
                                { (32u ^ sig), (48u ^ sig) } };
    uint32_t aBase[2], bBase[NI];
#pragma unroll
    for (int mi = 0; mi < 2; mi++)
        aBase[mi] = (uint32_t)((warpRow + mi * 16 + g) * 64 + tg * 4);
#pragma unroll
    for (int ni = 0; ni < NI; ni++)
        bBase[ni] = (uint32_t)(OFF_B + (warpCol + ni * 8 + g) * 64 + tg * 4);

    float acc[2][NI][4];
#pragma unroll
    for (int mi = 0; mi < 2; mi++)
#pragma unroll
        for (int ni = 0; ni < NI; ni++)
#pragma unroll
            for (int e = 0; e < 4; e++) acc[mi][ni][e] = 0.f;

    cp_stage_t<BN>(smbase + 0 * STAGE, aHp, bHp, 0,   tid);
    cp_stage_t<BN>(smbase + 1 * STAGE, aHp, bHp, 64,  tid);
    cp_stage_t<BN>(smbase + 2 * STAGE, aHp, bHp, 128, tid);

    for (int it = 0; it < 32; it++) {
        if (it < 30)       asm volatile("cp.async.wait_group 2;" ::: "memory");
        else if (it == 30) asm volatile("cp.async.wait_group 1;" ::: "memory");
        else               asm volatile("cp.async.wait_group 0;" ::: "memory");
        __syncthreads();
        if (it + 3 < 32)
            cp_stage_t<BN>(smbase + ((it + 3) & 3) * STAGE, aHp, bHp,
                           (it + 3) * 64, tid);
        const uint32_t so = smbase + (it & 3) * STAGE;

#pragma unroll
        for (int ks = 0; ks < 2; ks++) {
            const uint32_t k0 = kp[ks][0], k1 = kp[ks][1];
            uint32_t ahf[2][4];
#pragma unroll
            for (int mi = 0; mi < 2; mi++) {
                const uint32_t p0 = so + aBase[mi];
                ahf[mi][0] = *(const uint32_t*)__cvta_shared_to_generic(p0 + k0);
                ahf[mi][1] = *(const uint32_t*)__cvta_shared_to_generic(p0 + k0 + 512);
                ahf[mi][2] = *(const uint32_t*)__cvta_shared_to_generic(p0 + k1);
                ahf[mi][3] = *(const uint32_t*)__cvta_shared_to_generic(p0 + k1 + 512);
            }
            uint32_t bhf[NI][2];
#pragma unroll
            for (int ni = 0; ni < NI; ni++) {
                const uint32_t p0 = so + bBase[ni];
                bhf[ni][0] = *(const uint32_t*)__cvta_shared_to_generic(p0 + k0);
                bhf[ni][1] = *(const uint32_t*)__cvta_shared_to_generic(p0 + k1);
            }
#pragma unroll
            for (int mi = 0; mi < 2; mi++)
#pragma unroll
                for (int ni = 0; ni < NI; ni++)
                    mma_f16(acc[mi][ni], ahf[mi], bhf[ni]);
        }
    }

    // epilogue
#pragma unroll
    for (int mi = 0; mi < 2; mi++) {
        const int row0 = rowBase + warpRow + mi * 16 + g;
#pragma unroll
        for (int ni = 0; ni < NI; ni++) {
            const int col = colBase + warpCol + ni * 8 + tg * 2;
            float b0 = 0.f, b1 = 0.f;
            if (bias) { b0 = bias[col]; b1 = bias[col + 1]; }
            float2 v0 = make_float2(acc[mi][ni][0] + b0, acc[mi][ni][1] + b1);
            float2 v1 = make_float2(acc[mi][ni][2] + b0, acc[mi][ni][3] + b1);
            *reinterpret_cast<float2*>(&C[(size_t)row0 * DM + col]) = v0;
            *reinterpret_cast<float2*>(&C[(size_t)(row0 + 8) * DM + col]) = v1;
        }
    }
}

#define MM_SMEM_64  (4 * (4096 + 64 * 64))    // 32768

// ---------------------------------------------------------------------------
// persistent double-buffered fast-weight kernel, 128 threads/CTA.
// ---------------------------------------------------------------------------
#define FW_ITERS 8

__global__ __launch_bounds__(128, 6) void fastweight_kernel(
    const float* __restrict__ weights,
    const float* __restrict__ q, const float* __restrict__ k,
    const float* __restrict__ v, const float* __restrict__ beta,
    float* __restrict__ nw, __half* __restrict__ ohh)
{
    __shared__ __align__(16) float Wbuf[2][DK * DK];      // 2 x 16KB
    __shared__ __align__(16) float kqv[2][3][DK];         // k | q | v
    __shared__ float betasm[2];
    __shared__ float dsh[DK];

    const int t   = threadIdx.x;
    const int bh0 = blockIdx.x * FW_ITERS;

#define FW_PREFETCH(slot, bh)                                                   \
    do {                                                                        \
        const uint32_t sW = smaddr(&Wbuf[slot][0]);                             \
        const char* Wp = (const char*)(weights + (size_t)(bh) * (DK * DK));     \
        _Pragma("unroll")                                                       \
        for (int i = 0; i < 8; i++) {                                           \
            const uint32_t off = (uint32_t)(i * 128 + t) * 16;                  \
            cp16(sW + off, Wp + off);                                           \
        }                                                                       \
        const size_t gb = (size_t)((bh) >> 4) * DM + (size_t)((bh) & 15) * DK;  \
        if (t < 16)      cp16(smaddr(&kqv[slot][0][0]) + t * 16,                \
                              (const char*)(k + gb) + t * 16);                  \
        else if (t < 32) cp16(smaddr(&kqv[slot][1][0]) + (t - 16) * 16,         \
                              (const char*)(q + gb) + (t - 16) * 16);           \
        else if (t < 48) cp16(smaddr(&kqv[slot][2][0]) + (t - 32) * 16,         \
                              (const char*)(v + gb) + (t - 32) * 16);           \
        else if (t == 48) cp4(smaddr(&betasm[slot]), beta + (bh));              \
        asm volatile("cp.async.commit_group;");                                 \
    } while (0)

    FW_PREFETCH(0, bh0);

    for (int i = 0; i < FW_ITERS; i++) {
        const int slot = i & 1;
        if (i + 1 < FW_ITERS) {
            FW_PREFETCH((i + 1) & 1, bh0 + i + 1);
            asm volatile("cp.async.wait_group 1;" ::: "memory");
        } else {
            asm volatile("cp.async.wait_group 0;" ::: "memory");
        }
        __syncthreads();

        const int bh = bh0 + i;
        const float* Wsh = Wbuf[slot];
        const float* ksh = kqv[slot][0];
        const float* qsh = kqv[slot][1];
        const float  betav = betasm[slot];

        // phase 1 (threads 0-63): v_existing = row t . k (diagonal)
        if (t < DK) {
            const float vval = kqv[slot][2][t];
            float s = 0.f;
#pragma unroll
            for (int j = 0; j < DK; j++) {
                const int c = (j + t) & 63;
                s = fmaf(Wsh[t * DK + c], ksh[c], s);
            }
            dsh[t] = betav * (vval - s);
        }
        __syncthreads();

        // phase 2 (threads 0-63): out row t
        if (t < DK) {
            float s2 = 0.f, kq = 0.f;
#pragma unroll
            for (int j = 0; j < DK; j++) {
                const int c = (j + t) & 63;
                s2 = fmaf(Wsh[t * DK + c], qsh[c], s2);
                kq = fmaf(ksh[c], qsh[c], kq);
            }
            const float o = s2 + dsh[t] * kq;
            const size_t gb = (size_t)(bh >> 4) * DM + (size_t)(bh & 15) * DK + t;
            ohh[gb] = __float2half_rn(o);
        }

        // NW stream-out: 128 threads, thread t covers rows (t>>4)+8j, cols 4(t&15)
        float* NW = nw + (size_t)bh * (DK * DK);
        const int r0 = t >> 4, c4 = (t & 15) << 2;
        float4 k4;
        k4.x = ksh[c4 + 0]; k4.y = ksh[c4 + 1]; k4.z = ksh[c4 + 2]; k4.w = ksh[c4 + 3];
#pragma unroll 4
        for (int j = 0; j < 8; j++) {
            const int row = r0 + j * 8;
            const float d = dsh[row];
            const float4 w4 = *reinterpret_cast<const float4*>(&Wsh[row * DK + c4]);
            float4 o4;
            o4.x = w4.x + d * k4.x;
            o4.y = w4.y + d * k4.y;
            o4.z = w4.z + d * k4.z;
            o4.w = w4.w + d * k4.w;
            __stcs(reinterpret_cast<float4*>(&NW[row * DK + c4]), o4);
        }
        __syncthreads();
    }
#undef FW_PREFETCH
}

// ---------------------------------------------------------------------------
extern "C" void kernel_launch(void* const* d_in, const int* in_sizes, int n_in,
                              void* d_out, int out_size)
{
    const float* x       = (const float*)d_in[0];
    const float* weights = (const float*)d_in[1];
    const float* Wq      = (const float*)d_in[2];
    const float* Wk      = (const float*)d_in[3];
    const float* Wv      = (const float*)d_in[4];
    const float* Wg      = (const float*)d_in[5];
    const float* Wo      = (const float*)d_in[6];
    const float* bo      = (const float*)d_in[7];

    float* out = (float*)d_out;
    float* nw  = out + (size_t)BATCHN * DM;

    float *qb, *bb;
    __half *xh, *wt, *ohh;
    cudaGetSymbolAddress((void**)&qb,  g_qkv);
    cudaGetSymbolAddress((void**)&bb,  g_beta);
    cudaGetSymbolAddress((void**)&xh,  g_xh);
    cudaGetSymbolAddress((void**)&wt,  g_wt);
    cudaGetSymbolAddress((void**)&ohh, g_ohh);
    float* kb = qb + (size_t)BATCHN * DM;
    float* vb = kb + (size_t)BATCHN * DM;

    cudaFuncSetAttribute(mm_kernel<64, 4>,
                         cudaFuncAttributeMaxDynamicSharedMemorySize, MM_SMEM_64);

    const size_t MS = (size_t)DM * DM;

    // 1) transpose + fp16 the four big weight matrices
    transhalf_kernel<<<dim3(32, 32, 4), 256>>>(Wq, Wk, Wv, Wo, wt);
    // 2) fused x->fp16 + gate
    splitbeta_kernel<<<BATCHN, 256>>>(x, xh, Wg, bb);
    // 3) QKV projections (fused, grid.z = 3), 64x64 tiles -> 768 CTAs
    mm_kernel<64, 4><<<dim3(16, 16, 3), 256, MM_SMEM_64>>>(
        xh,
        wt + 0 * MS, wt + 1 * MS, wt + 2 * MS,
        qb, kb, vb, nullptr);
    // 4) persistent fast-weight update + read (nw -> d_out, outh fp16)
    fastweight_kernel<<<(BATCHN * HEADS) / FW_ITERS, 128>>>(
        weights, qb, kb, vb, bb, nw, ohh);
    // 5) output projection + bias, 64x64 tiles (256 CTAs)
    mm_kernel<64, 4><<<dim3(16, 16, 1), 256, MM_SMEM_64>>>(
        ohh,
        wt + 3 * MS, wt + 3 * MS, wt + 3 * MS,
        out, out, out, bo);
}

// round 16
// speedup vs baseline: 1.0637x; 1.0637x over previous
#include <cuda_runtime.h>
#include <cuda_fp16.h>
#include <cstdint>
#include <math.h>

#define DM     1024
#define BATCHN 1024
#define HEADS  16
#define DK     64

// ---------------- scratch (no allocation allowed) ----------------
__device__ float g_qkv[3u * BATCHN * DM];            // q | k | v fp32
__device__ float g_beta[BATCHN * HEADS];
__device__ __half g_xh[BATCHN * DM];                 // x fp16
__device__ __half g_wt[4u * DM * DM];                // W^T fp16: Wq,Wk,Wv,Wo
__device__ __half g_ohh[BATCHN * DM];                // outh fp16

__device__ __forceinline__ uint32_t smaddr(const void* p) {
    uint32_t a;
    asm("{ .reg .u64 t; cvta.to.shared.u64 t, %1; cvt.u32.u64 %0, t; }" : "=r"(a) : "l"(p));
    return a;
}
__device__ __forceinline__ void cp16(uint32_t s, const void* g) {
    asm volatile("cp.async.cg.shared.global [%0], [%1], 16;" :: "r"(s), "l"(g));
}
__device__ __forceinline__ void cp4(uint32_t s, const void* g) {
    asm volatile("cp.async.ca.shared.global [%0], [%1], 4;" :: "r"(s), "l"(g));
}
__device__ __forceinline__ void ldsm4(uint32_t* r, uint32_t addr) {
    asm volatile("ldmatrix.sync.aligned.m8n8.x4.shared.b16 {%0,%1,%2,%3}, [%4];"
        : "=r"(r[0]), "=r"(r[1]), "=r"(r[2]), "=r"(r[3]) : "r"(addr));
}

// ---------------------------------------------------------------------------
// fused: x -> fp16  AND  beta = sigmoid(x @ Wg). One CTA/batch.
// ---------------------------------------------------------------------------
__global__ __launch_bounds__(256) void splitbeta_kernel(
    const float* __restrict__ x, __half* __restrict__ hi,
    const float* __restrict__ Wg, float* __restrict__ beta)
{
    __shared__ float xs[DM];
    const int b = blockIdx.x, t = threadIdx.x;
    const int idx = b * 256 + t;
    float4 v = reinterpret_cast<const float4*>(x)[idx];
    float f[4] = {v.x, v.y, v.z, v.w};
    __half h[4];
#pragma unroll
    for (int i = 0; i < 4; i++) {
        h[i] = __float2half_rn(f[i]);
        xs[t * 4 + i] = f[i];
    }
    __half2* h2 = reinterpret_cast<__half2*>(hi);
    h2[idx * 2 + 0] = __half2(h[0], h[1]);
    h2[idx * 2 + 1] = __half2(h[2], h[3]);
    __syncthreads();

    const int w = t >> 5, lane = t & 31;
    const int hh = w * 2 + (lane >> 4);        // head for this half-warp
    const int lj = lane & 15;
    float s = 0.f;
#pragma unroll 8
    for (int i = 0; i < 64; i++) {
        const int j = lj + (i << 4);
        s = fmaf(xs[j], Wg[j * HEADS + hh], s);
    }
#pragma unroll
    for (int off = 8; off; off >>= 1) s += __shfl_xor_sync(0xffffffffu, s, off);
    if (lj == 0) beta[b * HEADS + hh] = 1.f / (1.f + expf(-s));
}

// ---------------------------------------------------------------------------
// transpose + fp16: W[K][N] -> Wt[N][K] fp16. z selects matrix.
// ---------------------------------------------------------------------------
__global__ __launch_bounds__(256) void transhalf_kernel(
    const float* __restrict__ W0, const float* __restrict__ W1,
    const float* __restrict__ W2, const float* __restrict__ W3,
    __half* __restrict__ H)
{
    __shared__ float tile[32][33];
    const int z = blockIdx.z;
    const float* W = (z == 0) ? W0 : (z == 1) ? W1 : (z == 2) ? W2 : W3;
    __half* Ht = H + (size_t)z * DM * DM;
    const int tx = threadIdx.x & 31, ty = threadIdx.x >> 5;
    const int nb = blockIdx.x * 32, kb = blockIdx.y * 32;
#pragma unroll
    for (int i = 0; i < 4; i++) {
        int k = kb + ty + i * 8;
        tile[ty + i * 8][tx] = W[(size_t)k * DM + nb + tx];
    }
    __syncthreads();
#pragma unroll
    for (int i = 0; i < 4; i++) {
        int n = nb + ty + i * 8;
        Ht[(size_t)n * DM + kb + tx] = __float2half_rn(tile[tx][ty + i * 8]);
    }
}

// ---------------------------------------------------------------------------
// single-pass fp16 GEMM on mma.sync + ldmatrix: C = A*B^T (fp32 accum).
// CTA tile 64xBN (BN=128 or 64), BK=32, 8 warps, 4-stage cp.async pipeline,
// XOR-swizzled 64B rows, one barrier / iteration.
// ---------------------------------------------------------------------------
#define OFF_B 4096

__device__ __forceinline__ void mma_f16(float* c, const uint32_t* a, const uint32_t* b) {
    asm volatile(
        "mma.sync.aligned.m16n8k16.row.col.f32.f16.f16.f32 "
        "{%0,%1,%2,%3}, {%4,%5,%6,%7}, {%8,%9}, {%0,%1,%2,%3};"
        : "+f"(c[0]), "+f"(c[1]), "+f"(c[2]), "+f"(c[3])
        : "r"(a[0]), "r"(a[1]), "r"(a[2]), "r"(a[3]), "r"(b[0]), "r"(b[1]));
}

template<int BN>
__device__ __forceinline__ void cp_stage_t(
    uint32_t smStage, const char* aH, const char* bH, int ktBytes, int tid)
{
    {   // A: 64 rows x 64B = 256 chunks; thread t -> row t>>2, chunk t&3
        const int r = tid >> 2, c = tid & 3;
        const int sw = (r >> 1) & 3;
        const size_t goff = ((size_t)r << 11) + (size_t)ktBytes + (c << 4);
        const uint32_t soff = r * 64 + ((c ^ sw) << 4);
        cp16(smStage + soff, aH + goff);
    }
    if (BN == 128) {   // B: 128 rows; thread t -> row t>>1, chunks (t&1)*2,+1
        const int r = tid >> 1;
        const int sw = (r >> 1) & 3;
#pragma unroll
        for (int cc = 0; cc < 2; cc++) {
            const int c = (tid & 1) * 2 + cc;
            const size_t goff = ((size_t)r << 11) + (size_t)ktBytes + (c << 4);
            const uint32_t soff = r * 64 + ((c ^ sw) << 4);
            cp16(smStage + OFF_B + soff, bH + goff);
        }
    } else {           // B: 64 rows; thread t -> row t>>2, chunk t&3
        const int r = tid >> 2, c = tid & 3;
        const int sw = (r >> 1) & 3;
        const size_t goff = ((size_t)r << 11) + (size_t)ktBytes + (c << 4);
        const uint32_t soff = r * 64 + ((c ^ sw) << 4);
        cp16(smStage + OFF_B + soff, bH + goff);
    }
    asm volatile("cp.async.commit_group;");
}

template<int BN, int MINB>
__global__ __launch_bounds__(256, MINB) void mm_kernel(
    const __half* __restrict__ Ah,
    const __half* __restrict__ Bt0, const __half* __restrict__ Bt1,
    const __half* __restrict__ Bt2,
    float* __restrict__ C0, float* __restrict__ C1, float* __restrict__ C2,
    const float* __restrict__ bias)
{
    constexpr int STAGE = 4096 + BN * 64;
    constexpr int NI = BN / 32;
    extern __shared__ char sm[];
    uint32_t smbase;
    asm("{ .reg .u64 t; cvta.to.shared.u64 t, %1; cvt.u32.u64 %0, t; }"
        : "=r"(smbase) : "l"(sm));

    const int tid = threadIdx.x;
    const int warp = tid >> 5, lane = tid & 31;
    const int g = lane >> 2, tg = lane & 3;
    const int z = blockIdx.z;
    const __half* Bt = (z == 0) ? Bt0 : (z == 1) ? Bt1 : Bt2;
    float* C = (z == 0) ? C0 : (z == 1) ? C1 : C2;

    const int rowBase = blockIdx.y * 64;
    const int colBase = blockIdx.x * BN;
    const int warpRow = (warp & 1) * 32;
    const int warpCol = (warp >> 1) * (BN / 4);

    const char* aHp = (const char*)Ah + ((size_t)rowBase << 11);
    const char* bHp = (const char*)Bt + ((size_t)colBase << 11);

    // ldmatrix lane addressing. All row bases are multiples of 8, so the
    // swizzle selector reduces to bits 1-2 of (lane&7) for every fragment row.
    const uint32_t swz = (uint32_t)((lane & 7) >> 1);        // 0..3
    const uint32_t aChunkSel = (uint32_t)(lane >> 4);        // 16B half for A
    const uint32_t bChunkSel = (uint32_t)((lane >> 3) & 1);  // 16B half for B
    // A: matrices (rows 0-7 lo | rows 8-15 lo | rows 0-7 hi | rows 8-15 hi)
    uint32_t aRowOff[2];
#pragma unroll
    for (int mi = 0; mi < 2; mi++)
        aRowOff[mi] = (uint32_t)((warpRow + mi * 16 + ((lane >> 3) & 1) * 8 + (lane & 7)) * 64);
    // B: matrices (n 0-7 k-lo | n 0-7 k-hi | n 8-15 k-lo | n 8-15 k-hi)
    uint32_t bRowOff[NI / 2];
#pragma unroll
    for (int p = 0; p < NI / 2; p++)
        bRowOff[p] = (uint32_t)(OFF_B + (warpCol + p * 16 + (lane >> 4) * 8 + (lane & 7)) * 64);

    float acc[2][NI][4];
#pragma unroll
    for (int mi = 0; mi < 2; mi++)
#pragma unroll
        for (int ni = 0; ni < NI; ni++)
#pragma unroll
            for (int e = 0; e < 4; e++) acc[mi][ni][e] = 0.f;

    cp_stage_t<BN>(smbase + 0 * STAGE, aHp, bHp, 0,   tid);
    cp_stage_t<BN>(smbase + 1 * STAGE, aHp, bHp, 64,  tid);
    cp_stage_t<BN>(smbase + 2 * STAGE, aHp, bHp, 128, tid);

    for (int it = 0; it < 32; it++) {
        if (it < 30)       asm volatile("cp.async.wait_group 2;" ::: "memory");
        else if (it == 30) asm volatile("cp.async.wait_group 1;" ::: "memory");
        else               asm volatile("cp.async.wait_group 0;" ::: "memory");
        __syncthreads();
        if (it + 3 < 32)
            cp_stage_t<BN>(smbase + ((it + 3) & 3) * STAGE, aHp, bHp,
                           (it + 3) * 64, tid);
        const uint32_t so = smbase + (it & 3) * STAGE;

#pragma unroll
        for (int ks = 0; ks < 2; ks++) {
            const uint32_t aCh = (((uint32_t)(ks * 2) + aChunkSel) ^ swz) << 4;
            const uint32_t bCh = (((uint32_t)(ks * 2) + bChunkSel) ^ swz) << 4;
            uint32_t ahf[2][4];
#pragma unroll
            for (int mi = 0; mi < 2; mi++)
                ldsm4(&ahf[mi][0], so + aRowOff[mi] + aCh);
            uint32_t bhf[NI][2];
#pragma unroll
            for (int p = 0; p < NI / 2; p++)
                ldsm4(&bhf[p * 2][0], so + bRowOff[p] + bCh);
#pragma unroll
            for (int mi = 0; mi < 2; mi++)
#pragma unroll
                for (int ni = 0; ni < NI; ni++)
                    mma_f16(acc[mi][ni], ahf[mi], bhf[ni]);
        }
    }

    // epilogue
#pragma unroll
    for (int mi = 0; mi < 2; mi++) {
        const int row0 = rowBase + warpRow + mi * 16 + g;
#pragma unroll
        for (int ni = 0; ni < NI; ni++) {
            const int col = colBase + warpCol + ni * 8 + tg * 2;
            float b0 = 0.f, b1 = 0.f;
            if (bias) { b0 = bias[col]; b1 = bias[col + 1]; }
            float2 v0 = make_float2(acc[mi][ni][0] + b0, acc[mi][ni][1] + b1);
            float2 v1 = make_float2(acc[mi][ni][2] + b0, acc[mi][ni][3] + b1);
            *reinterpret_cast<float2*>(&C[(size_t)row0 * DM + col]) = v0;
            *reinterpret_cast<float2*>(&C[(size_t)(row0 + 8) * DM + col]) = v1;
        }
    }
}

#define MM_SMEM_128 (4 * (4096 + 128 * 64))   // 49152
#define MM_SMEM_64  (4 * (4096 + 64 * 64))    // 32768

// ---------------------------------------------------------------------------
// persistent double-buffered fast-weight kernel, 128 threads/CTA.
// ---------------------------------------------------------------------------
#define FW_ITERS 8

__global__ __launch_bounds__(128, 6) void fastweight_kernel(
    const float* __restrict__ weights,
    const float* __restrict__ q, const float* __restrict__ k,
    const float* __restrict__ v, const float* __restrict__ beta,
    float* __restrict__ nw, __half* __restrict__ ohh)
{
    __shared__ __align__(16) float Wbuf[2][DK * DK];      // 2 x 16KB
    __shared__ __align__(16) float kqv[2][3][DK];         // k | q | v
    __shared__ float betasm[2];
    __shared__ float dsh[DK];

    const int t   = threadIdx.x;
    const int bh0 = blockIdx.x * FW_ITERS;

#define FW_PREFETCH(slot, bh)                                                   \
    do {                                                                        \
        const uint32_t sW = smaddr(&Wbuf[slot][0]);                             \
        const char* Wp = (const char*)(weights + (size_t)(bh) * (DK * DK));     \
        _Pragma("unroll")                                                       \
        for (int i = 0; i < 8; i++) {                                           \
            const uint32_t off = (uint32_t)(i * 128 + t) * 16;                  \
            cp16(sW + off, Wp + off);                                           \
        }                                                                       \
        const size_t gb = (size_t)((bh) >> 4) * DM + (size_t)((bh) & 15) * DK;  \
        if (t < 16)      cp16(smaddr(&kqv[slot][0][0]) + t * 16,                \
                              (const char*)(k + gb) + t * 16);                  \
        else if (t < 32) cp16(smaddr(&kqv[slot][1][0]) + (t - 16) * 16,         \
                              (const char*)(q + gb) + (t - 16) * 16);           \
        else if (t < 48) cp16(smaddr(&kqv[slot][2][0]) + (t - 32) * 16,         \
                              (const char*)(v + gb) + (t - 32) * 16);           \
        else if (t == 48) cp4(smaddr(&betasm[slot]), beta + (bh));              \
        asm volatile("cp.async.commit_group;");                                 \
    } while (0)

    FW_PREFETCH(0, bh0);

    for (int i = 0; i < FW_ITERS; i++) {
        const int slot = i & 1;
        if (i + 1 < FW_ITERS) {
            FW_PREFETCH((i + 1) & 1, bh0 + i + 1);
            asm volatile("cp.async.wait_group 1;" ::: "memory");
        } else {
            asm volatile("cp.async.wait_group 0;" ::: "memory");
        }
        __syncthreads();

        const int bh = bh0 + i;
        const float* Wsh = Wbuf[slot];
        const float* ksh = kqv[slot][0];
        const float* qsh = kqv[slot][1];
        const float  betav = betasm[slot];

        // phase 1 (threads 0-63): v_existing = row t . k (diagonal)
        if (t < DK) {
            const float vval = kqv[slot][2][t];
            float s = 0.f;
#pragma unroll
            for (int j = 0; j < DK; j++) {
                const int c = (j + t) & 63;
                s = fmaf(Wsh[t * DK + c], ksh[c], s);
            }
            dsh[t] = betav * (vval - s);
        }
        __syncthreads();

        // phase 2 (threads 0-63): out row t
        if (t < DK) {
            float s2 = 0.f, kq = 0.f;
#pragma unroll
            for (int j = 0; j < DK; j++) {
                const int c = (j + t) & 63;
                s2 = fmaf(Wsh[t * DK + c], qsh[c], s2);
                kq = fmaf(ksh[c], qsh[c], kq);
            }
            const float o = s2 + dsh[t] * kq;
            const size_t gb = (size_t)(bh >> 4) * DM + (size_t)(bh & 15) * DK + t;
            ohh[gb] = __float2half_rn(o);
        }

        // NW stream-out: 128 threads, thread t covers rows (t>>4)+8j, cols 4(t&15)
        float* NW = nw + (size_t)bh * (DK * DK);
        const int r0 = t >> 4, c4 = (t & 15) << 2;
        float4 k4;
        k4.x = ksh[c4 + 0]; k4.y = ksh[c4 + 1]; k4.z = ksh[c4 + 2]; k4.w = ksh[c4 + 3];
#pragma unroll 4
        for (int j = 0; j < 8; j++) {
            const int row = r0 + j * 8;
            const float d = dsh[row];
            const float4 w4 = *reinterpret_cast<const float4*>(&Wsh[row * DK + c4]);
            float4 o4;
            o4.x = w4.x + d * k4.x;
            o4.y = w4.y + d * k4.y;
            o4.z = w4.z + d * k4.z;
            o4.w = w4.w + d * k4.w;
            __stcs(reinterpret_cast<float4*>(&NW[row * DK + c4]), o4);
        }
        __syncthreads();
    }
#undef FW_PREFETCH
}

// ---------------------------------------------------------------------------
extern "C" void kernel_launch(void* const* d_in, const int* in_sizes, int n_in,
                              void* d_out, int out_size)
{
    const float* x       = (const float*)d_in[0];
    const float* weights = (const float*)d_in[1];
    const float* Wq      = (const float*)d_in[2];
    const float* Wk      = (const float*)d_in[3];
    const float* Wv      = (const float*)d_in[4];
    const float* Wg      = (const float*)d_in[5];
    const float* Wo      = (const float*)d_in[6];
    const float* bo      = (const float*)d_in[7];

    float* out = (float*)d_out;
    float* nw  = out + (size_t)BATCHN * DM;

    float *qb, *bb;
    __half *xh, *wt, *ohh;
    cudaGetSymbolAddress((void**)&qb,  g_qkv);
    cudaGetSymbolAddress((void**)&bb,  g_beta);
    cudaGetSymbolAddress((void**)&xh,  g_xh);
    cudaGetSymbolAddress((void**)&wt,  g_wt);
    cudaGetSymbolAddress((void**)&ohh, g_ohh);
    float* kb = qb + (size_t)BATCHN * DM;
    float* vb = kb + (size_t)BATCHN * DM;

    cudaFuncSetAttribute(mm_kernel<128, 3>,
                         cudaFuncAttributeMaxDynamicSharedMemorySize, MM_SMEM_128);
    cudaFuncSetAttribute(mm_kernel<64, 4>,
                         cudaFuncAttributeMaxDynamicSharedMemorySize, MM_SMEM_64);

    const size_t MS = (size_t)DM * DM;

    // 1) transpose + fp16 the four big weight matrices
    transhalf_kernel<<<dim3(32, 32, 4), 256>>>(Wq, Wk, Wv, Wo, wt);
    // 2) fused x->fp16 + gate
    splitbeta_kernel<<<BATCHN, 256>>>(x, xh, Wg, bb);
    // 3) QKV projections (fused, grid.z = 3), 64x128 tiles
    mm_kernel<128, 3><<<dim3(8, 16, 3), 256, MM_SMEM_128>>>(
        xh,
        wt + 0 * MS, wt + 1 * MS, wt + 2 * MS,
        qb, kb, vb, nullptr);
    // 4) persistent fast-weight update + read (nw -> d_out, outh fp16)
    fastweight_kernel<<<(BATCHN * HEADS) / FW_ITERS, 128>>>(
        weights, qb, kb, vb, bb, nw, ohh);
    // 5) output projection + bias, 64x64 tiles (256 CTAs)
    mm_kernel<64, 4><<<dim3(16, 16, 1), 256, MM_SMEM_64>>>(
        ohh,
        wt + 3 * MS, wt + 3 * MS, wt + 3 * MS,
        out, out, out, bo);
}